// round 14
// baseline (speedup 1.0000x reference)
#include <cuda_runtime.h>

// Depth-to-space k=3 (CRD): out[b, 3i+r, 3j+s] = in[b, 3r+s, i, j]
//   in : (32, 9, 512, 512) fp32   out: (32, 1, 1536, 1536) fp32
//
// R8 -> R14: identical per-row body (18 coalesced streaming LDG.32/thread,
// stride-3 conflict-free smem scatter, coalesced float4 streaming stores),
// but a PERSISTENT grid of exactly 148*8 blocks grid-striding over the
// 16384 rows. Removes the 13 wave transitions (~2360 cyc each) and the
// fractional final wave of the R8 launch -- the only remaining scheduling
// bubble in the DRAM request supply. No registers live across barriers
// (unlike the failed R9 pipeline), so regs/occupancy match R8 exactly.
//
// 256 thr, 18KB smem -> 8 blocks/SM = full 2048 threads.

#define THREADS 256
#define ROW3 4608            // 3 * 1536 floats = 18KB
#define NROWS 16384          // 32 batches * 512 input rows
#define GRID  (148 * 8)

__global__ __launch_bounds__(THREADS) void d2s_k3_persist_kernel(
    const float* __restrict__ in, float* __restrict__ out)
{
    __shared__ float rows[ROW3];

    const int tid = threadIdx.x;

    for (int bi = blockIdx.x; bi < NROWS; bi += GRID) {
        const int i = bi & 511;
        const int b = bi >> 9;

        const float* ip = in + (size_t)b * 9 * 262144 + (size_t)i * 512;

        // 18 fully-coalesced, independent streaming loads per thread
        #pragma unroll
        for (int l = 0; l < 18; ++l) {
            int t   = tid + l * THREADS;   // 0..4607
            int c   = t >> 9;              // channel 0..8 (const per l)
            int col = t & 511;
            float v = __ldcs(ip + c * 262144 + col);
            int r = c / 3;
            int s = c - 3 * r;
            rows[r * 1536 + 3 * col + s] = v;   // conflict-free scatter
        }

        __syncthreads();

        // 18KB contiguous output rows 3i..3i+2, coalesced float4
        const float4* rv = reinterpret_cast<const float4*>(rows);
        float4* op = reinterpret_cast<float4*>(
            out + (size_t)(b * 1536 + 3 * i) * 1536);

        #pragma unroll
        for (int l = 0; l < 4; ++l)
            __stcs(&op[tid + l * THREADS], rv[tid + l * THREADS]);
        if (tid < 128)
            __stcs(&op[tid + 1024], rv[tid + 1024]);

        __syncthreads();   // protect smem from next iteration's scatter
    }
}

extern "C" void kernel_launch(void* const* d_in, const int* in_sizes, int n_in,
                              void* d_out, int out_size)
{
    const float* in  = (const float*)d_in[0];
    float*       out = (float*)d_out;

    d2s_k3_persist_kernel<<<GRID, THREADS>>>(in, out);
}

// round 15
// speedup vs baseline: 1.1542x; 1.1542x over previous
#include <cuda_runtime.h>

// Depth-to-space k=3 (CRD): out[b, 3i+r, 3j+s] = in[b, 3r+s, i, j]
//   in : (32, 9, 512, 512) fp32   out: (32, 1, 1536, 1536) fp32
//
// FINAL CHAMPION (R8 config; reproduced at 90.2 / 90.4 us, rel_err 0).
// One block per INPUT row (b, i) -> 3 contiguous output rows (18KB).
//
//  - 18 independent, fully-coalesced streaming LDG.32 per thread
//  - stride-3 word scatter into smem: gcd(3,32)=1 -> bank-conflict-free
//  - ONE barrier per block lifetime (fresh blocks each row: load/store
//    phases of successive rows overlap via the block scheduler for free --
//    persistent-grid and SW-pipeline variants both measured SLOWER)
//  - coalesced float4 streaming stores of 18KB contiguous output
//  - 256 thr x 18KB smem -> 8 blocks/SM = full 2048 threads
//
// Measured across 7 structural variants: ~6.4 TB/s mixed R/W (80% of HBM
// spec) is the ceiling for this touch-once permutation; DRAM-bound with
// L2/L1/issue all <45%. No SM-side lever moves it.

#define THREADS 256
#define ROW3 4608            // 3 * 1536 floats = 18KB

__global__ __launch_bounds__(THREADS) void d2s_k3_row3_b256_kernel(
    const float* __restrict__ in, float* __restrict__ out)
{
    __shared__ float rows[ROW3];

    const int tid = threadIdx.x;
    const int bi  = blockIdx.x;        // b*512 + i
    const int i   = bi & 511;
    const int b   = bi >> 9;

    // base of (batch b, input row i), channel 0
    const float* ip = in + (size_t)b * 9 * 262144 + (size_t)i * 512;

    // 18 fully-coalesced, independent streaming loads per thread
    #pragma unroll
    for (int l = 0; l < 18; ++l) {
        int t   = tid + l * THREADS;   // 0..4607
        int c   = t >> 9;              // channel 0..8 (compile-time per l)
        int col = t & 511;             // input column
        float v = __ldcs(ip + c * 262144 + col);
        int r = c / 3;
        int s = c - 3 * r;
        rows[r * 1536 + 3 * col + s] = v;   // conflict-free stride-3 scatter
    }

    __syncthreads();

    // 18KB contiguous output: rows 3i..3i+2 of batch b, coalesced float4
    const float4* rv = reinterpret_cast<const float4*>(rows);
    float4* op = reinterpret_cast<float4*>(
        out + (size_t)(b * 1536 + 3 * i) * 1536);

    #pragma unroll
    for (int l = 0; l < 4; ++l)
        __stcs(&op[tid + l * THREADS], rv[tid + l * THREADS]);
    if (tid < 128)
        __stcs(&op[tid + 1024], rv[tid + 1024]);
}

extern "C" void kernel_launch(void* const* d_in, const int* in_sizes, int n_in,
                              void* d_out, int out_size)
{
    const float* in  = (const float*)d_in[0];
    float*       out = (float*)d_out;

    d2s_k3_row3_b256_kernel<<<32 * 512, THREADS>>>(in, out);
}